// round 6
// baseline (speedup 1.0000x reference)
#include <cuda_runtime.h>
#include <cuda_fp16.h>
#include <cstdint>

// ============================================================================
// Hopf CPG step via mma.sync (HMMA, tf32) — baseline PTX, no sm_103a-only ops.
//   sin(psi_j - psi_i - phi_ij) = (s_j c_i - c_j s_i)cosφ - (c_j c_i + s_j s_i)sinφ
//   A = w_zd cosφ, B = w_zd sinφ, x = r·s, y = r·c
//   P = A x - B y, Q = A y + B x,  psi_dot_i = 2πV·σ(v_i) + c_i P_i - s_i Q_i
// Per 64-row tile: Z = [x|y] (64x64), W[k][n] = [[Aᵀ, Bᵀ], [-Bᵀ, Aᵀ]] (64x64),
// [P|Q] = Z @ W via m16n8k8 tf32 mma (8 kt x 8 nt per warp-m16-tile).
// ============================================================================

#define PI2F 6.28318530717958647692f
#define ZS   68     // Z/W row stride in floats (bank-spread: 68%32=4)
#define SCS  34     // sc row stride in uints

__device__ __forceinline__ float tf32r(float x) {
    float r;
    asm("cvt.rna.tf32.f32 %0, %1;" : "=f"(r) : "f"(x));
    return r;
}
__device__ __forceinline__ float fsigmoid(float x) { return 1.0f / (1.0f + __expf(-x)); }

#define MMA_TF32(d0,d1,d2,d3, a0,a1,a2,a3, b0,b1) \
    asm volatile("mma.sync.aligned.m16n8k8.row.col.f32.tf32.tf32.f32 " \
        "{%0,%1,%2,%3}, {%4,%5,%6,%7}, {%8,%9}, {%0,%1,%2,%3};" \
        : "+f"(d0), "+f"(d1), "+f"(d2), "+f"(d3) \
        : "r"(a0), "r"(a1), "r"(a2), "r"(a3), "r"(b0), "r"(b1))

// dynamic smem float layout:
//   Z   [0,     4352)   64 x 68
//   W   [4352,  8704)   64 x 68
//   SC  [8704, 10880)   64 x 34 (uint half2 {c,s})
//   TPV [10880,10912)  BA [10912,10944)  CA [10944,10976)
#define SM_Z    0
#define SM_W    4352
#define SM_SC   8704
#define SM_TPV  10880
#define SM_BA   10912
#define SM_CA   10944
#define SM_FLOATS 10976

__global__ __launch_bounds__(128, 5)
void hopf_mma(const float* __restrict__ in, float* __restrict__ out,
              const float* __restrict__ v, const float* __restrict__ b,
              const float* __restrict__ c, const float* __restrict__ w,
              const float* __restrict__ phi, int nrows, int ntiles) {
    extern __shared__ float sm[];
    float* Z  = sm + SM_Z;
    float* W  = sm + SM_W;
    uint32_t* SC = (uint32_t*)(sm + SM_SC);

    const int tid  = threadIdx.x;
    const int wid  = tid >> 5;
    const int lane = tid & 31;
    const int g    = lane >> 2;   // group id (0..7)
    const int tig  = lane & 3;    // thread in group (0..3)

    // ---- per-oscillator activations ----
    if (tid < 32) {
        sm[SM_TPV + tid] = (PI2F * 5.0f) * fsigmoid(v[tid]);
        sm[SM_BA  + tid] = 2.0f  * fsigmoid(b[tid]);
        sm[SM_CA  + tid] = 10.0f * fsigmoid(c[tid]);
    }

    // ---- build W once per CTA: W[k][n] (tf32-rounded) ----
    #pragma unroll
    for (int e = 0; e < 8; e++) {
        int m = tid + e * 128;            // flat i*32+j over A/B entries
        float A = 0.0f, Bv = 0.0f;
        if (m % 33 != 0) {                // zero-diag
            int kk = m / 33, jj = m % 33 - 1;
            float wa = fsigmoid(w[kk * 32 + jj]);            // W_MAX=1
            float pa = PI2F * fsigmoid(phi[kk * 32 + jj]);   // PHI_MAX=2pi
            float sp, cp;
            __sincosf(pa, &sp, &cp);
            A = tf32r(wa * cp);  Bv = tf32r(wa * sp);
        }
        int i = m >> 5, j = m & 31;
        W[j        * ZS + i     ] =  A;    // k<32,  n<32 :  A[i][j]
        W[j        * ZS + i + 32] =  Bv;   // k<32,  n>=32:  B[i][j]
        W[(j + 32) * ZS + i     ] = -Bv;   // k>=32, n<32 : -B[i][j]
        W[(j + 32) * ZS + i + 32] =  A;    // k>=32, n>=32:  A[i][j]
    }
    __syncthreads();

    const float2* tpv2 = (const float2*)(sm + SM_TPV);

    for (int tile = blockIdx.x; tile < ntiles; tile += gridDim.x) {
        const int rowBase = tile * 64;

        // ---- prologue: 16 elements/thread, coalesced ----
        #pragma unroll
        for (int s = 0; s < 16; s++) {
            int e = tid + s * 128;
            int rl = e >> 5, ln = e & 31;
            int row = rowBase + rl;
            float psi = 0.0f, rr = 0.0f, rd = 0.0f;
            if (row < nrows) {
                const float* rp = in + (size_t)row * 96;
                psi = rp[ln];  rr = rp[32 + ln];  rd = rp[64 + ln];
            }
            float sv, cv;
            __sincosf(psi, &sv, &cv);
            Z[rl * ZS + ln]      = tf32r(rr * sv);   // x
            Z[rl * ZS + 32 + ln] = tf32r(rr * cv);   // y
            __half2 h = __floats2half2_rn(cv, sv);   // lo=c, hi=s
            SC[rl * SCS + ln] = *(uint32_t*)&h;
            if (row < nrows) {
                float ba = sm[SM_BA + ln], ca = sm[SM_CA + ln];
                float rdd = ca * (0.25f * ca * (ba - rr) - rd);
                float* op = out + (size_t)row * 96;
                op[32 + ln] = rd;
                op[64 + ln] = rdd;
            }
        }
        __syncthreads();

        // ---- mma: warp owns 16 rows (m16), 8 n-tiles, 8 k-steps ----
        const int mrow = wid * 16;
        float acc[8][4];
        #pragma unroll
        for (int nt = 0; nt < 8; nt++)
            #pragma unroll
            for (int q = 0; q < 4; q++) acc[nt][q] = 0.0f;

        #pragma unroll
        for (int kt = 0; kt < 8; kt++) {
            const int k0 = kt * 8;
            uint32_t a0 = __float_as_uint(Z[(mrow + g)     * ZS + k0 + tig]);
            uint32_t a1 = __float_as_uint(Z[(mrow + g + 8) * ZS + k0 + tig]);
            uint32_t a2 = __float_as_uint(Z[(mrow + g)     * ZS + k0 + tig + 4]);
            uint32_t a3 = __float_as_uint(Z[(mrow + g + 8) * ZS + k0 + tig + 4]);
            const float* wr0 = W + (k0 + tig)     * ZS + g;
            const float* wr1 = W + (k0 + tig + 4) * ZS + g;
            #pragma unroll
            for (int nt = 0; nt < 8; nt++) {
                uint32_t b0 = __float_as_uint(wr0[nt * 8]);
                uint32_t b1 = __float_as_uint(wr1[nt * 8]);
                MMA_TF32(acc[nt][0], acc[nt][1], acc[nt][2], acc[nt][3],
                         a0, a1, a2, a3, b0, b1);
            }
        }

        // ---- epilogue: psi_dot = tpv + c*P - s*Q, bounce into Z cols 0..31 ----
        #pragma unroll
        for (int nt = 0; nt < 4; nt++) {
            int col = nt * 8 + 2 * tig;          // even, 8B-aligned pairs
            float2 tp = tpv2[col >> 1];
            #pragma unroll
            for (int rs = 0; rs < 2; rs++) {     // rows g, g+8
                int rl = mrow + g + rs * 8;
                uint2 hh = *(const uint2*)&SC[rl * SCS + col];
                __half2 h0 = *(__half2*)&hh.x, h1 = *(__half2*)&hh.y;
                float c0 = __low2float(h0), s0 = __high2float(h0);
                float c1 = __low2float(h1), s1 = __high2float(h1);
                float P0 = acc[nt][rs * 2], P1 = acc[nt][rs * 2 + 1];
                float Q0 = acc[nt + 4][rs * 2], Q1 = acc[nt + 4][rs * 2 + 1];
                float2 pd;
                pd.x = tp.x + c0 * P0 - s0 * Q0;
                pd.y = tp.y + c1 * P1 - s1 * Q1;
                *(float2*)&Z[rl * ZS + col] = pd;
            }
        }
        __syncthreads();

        // ---- coalesced psi_dot copy-out ----
        #pragma unroll
        for (int s = 0; s < 16; s++) {
            int e = tid + s * 128;
            int rl = e >> 5, ln = e & 31;
            int row = rowBase + rl;
            if (row < nrows) out[(size_t)row * 96 + ln] = Z[rl * ZS + ln];
        }
        __syncthreads();
    }
}

extern "C" void kernel_launch(void* const* d_in, const int* in_sizes, int n_in,
                              void* d_out, int out_size) {
    const float* states = (const float*)d_in[0];
    const float* v      = (const float*)d_in[1];
    const float* b      = (const float*)d_in[2];
    const float* c      = (const float*)d_in[3];
    const float* w      = (const float*)d_in[4];
    const float* phi    = (const float*)d_in[5];
    float* out = (float*)d_out;

    const int nrows  = in_sizes[0] / 96;              // 65536
    const int ntiles = (nrows + 63) / 64;             // 1024
    int grid = ntiles < 512 ? ntiles : 512;           // ~2 tiles/CTA, <=1 wave

    static int smem_set = 0;
    if (!smem_set) {
        cudaFuncSetAttribute(hopf_mma, cudaFuncAttributeMaxDynamicSharedMemorySize,
                             SM_FLOATS * 4);
        smem_set = 1;
    }
    hopf_mma<<<grid, 128, SM_FLOATS * 4>>>(states, out, v, b, c, w, phi, nrows, ntiles);
}